// round 12
// baseline (speedup 1.0000x reference)
#include <cuda_runtime.h>
#include <cuda_fp16.h>
#include <cstdint>

#define M_TOT 25088
#define ASTG 10240          // A bytes/stage: 128 n-rows padded to 80B
#define BSTG 4608           // B bytes/stage: 16 kp-rows x 64 m (u32), padded to 288B
#define STG  14848
#define DSMEM 34816         // epilogue [128][68] f32 dominates

__device__ __align__(256) uint32_t g_Bh[12845056];        // hbar fp16 [512 kp][25088 m], k-pair packed
__device__ __align__(256) unsigned short g_wh[262144];    // W fp16 [n][k]

__device__ __forceinline__ int rmap(int p) { int q = p / 7, r = p - q * 7; return q * 6 + (r < 5 ? r : 5) + 4; }
__device__ __forceinline__ uint32_t smem_u32(const void* p) {
    uint32_t a; asm("{ .reg .u64 t; cvta.to.shared.u64 t, %1; cvt.u32.u64 %0, t; }" : "=r"(a) : "l"(p)); return a;
}
__device__ __forceinline__ uint32_t lds32(uint32_t a) {
    uint32_t v; asm volatile("ld.shared.u32 %0, [%1];" : "=r"(v) : "r"(a)); return v;
}

#define MMA(c, a, b0, b1) asm volatile( \
    "mma.sync.aligned.m16n8k16.row.col.f32.f16.f16.f32 {%0,%1,%2,%3}, {%4,%5,%6,%7}, {%8,%9}, {%0,%1,%2,%3};" \
    : "+f"((c)[0]), "+f"((c)[1]), "+f"((c)[2]), "+f"((c)[3]) \
    : "r"((a)[0]), "r"((a)[1]), "r"((a)[2]), "r"((a)[3]), "r"(b0), "r"(b1))
#define CPA(d, s) asm volatile("cp.async.cg.shared.global [%0], [%1], 16;" :: "r"(d), "l"(s))

// ---- pass1 (+ folded W prep): blocks >= 8192 convert W; others do gather+BN+ReLU+pool
__global__ __launch_bounds__(256) void pass1_kernel(const float* __restrict__ x,
        const float* __restrict__ gamma, const float* __restrict__ beta,
        const float* __restrict__ mean, const float* __restrict__ var,
        const float* __restrict__ w) {
    __shared__ float s[2][3136];
    int t = threadIdx.x, blk = blockIdx.x;

    if (blk >= 8192) {                           // W f32 -> fp16 [n][k], 4 elems/thread
        int i = (blk - 8192) * 256 + t;          // 0..65535
        float4 v = *(const float4*)(w + (size_t)i * 4);
        __half2 p0 = __floats2half2_rn(v.x, v.y);
        __half2 p1 = __floats2half2_rn(v.z, v.w);
        *(uint2*)(g_wh + (size_t)i * 4) = make_uint2(*(uint32_t*)&p0, *(uint32_t*)&p1);
        return;
    }

    int b = blk & 31, cp = blk >> 5;             // cp 0..255 -> channels 2cp, 2cp+1
#pragma unroll
    for (int pl = 0; pl < 2; ++pl) {
        const float4* xp4 = (const float4*)(x + ((size_t)(b * 512 + 2 * cp + pl)) * 3136);
        float4* s4 = (float4*)s[pl];
        // 784 float4 = 3*256 + 16
        s4[t] = xp4[t];
        s4[t + 256] = xp4[t + 256];
        s4[t + 512] = xp4[t + 512];
        if (t < 16) s4[t + 768] = xp4[t + 768];
    }
    __syncthreads();
    if (t >= 196) return;
    int ij0 = 4 * t, i = ij0 / 28, j0 = ij0 - i * 28;
#pragma unroll
    for (int g = 0; g < 2; ++g) {                // g=0 direct, g=1 gathered (+512)
        unsigned short hh[2][4];
#pragma unroll
        for (int pl = 0; pl < 2; ++pl) {
            int c2 = 2 * cp + pl + g * 512;
            float inv = gamma[c2] * rsqrtf(var[c2] + 1e-5f);
            float bias = fmaf(-mean[c2], inv, beta[c2]);
            const float* r0; const float* r1;
            if (!g) { r0 = s[pl] + (2 * i) * 56; r1 = r0 + 56; }
            else { r0 = s[pl] + rmap(2 * i) * 56; r1 = s[pl] + rmap(2 * i + 1) * 56; }
#pragma unroll
            for (int u = 0; u < 4; ++u) {
                int jj = j0 + u;
                int q0 = g ? rmap(2 * jj) : 2 * jj;
                int q1 = g ? rmap(2 * jj + 1) : 2 * jj + 1;
                float o = 0.25f * (fmaxf(fmaf(r0[q0], inv, bias), 0.0f) + fmaxf(fmaf(r0[q1], inv, bias), 0.0f)
                                 + fmaxf(fmaf(r1[q0], inv, bias), 0.0f) + fmaxf(fmaf(r1[q1], inv, bias), 0.0f));
                __half hv = __float2half_rn(o);
                hh[pl][u] = *(unsigned short*)&hv;
            }
        }
        size_t base = (size_t)(g * 256 + cp) * M_TOT + b * 784 + ij0;
        uint4 vh;
        vh.x = hh[0][0] | ((uint32_t)hh[1][0] << 16); vh.y = hh[0][1] | ((uint32_t)hh[1][1] << 16);
        vh.z = hh[0][2] | ((uint32_t)hh[1][2] << 16); vh.w = hh[0][3] | ((uint32_t)hh[1][3] << 16);
        *(uint4*)(g_Bh + base) = vh;
    }
}

// ---- pass2: fp16 HMMA GEMM, tile 128n x 64m, occ 3. D[n][m] = sum_k W[n][k]*hbar[k][m]
__global__ __launch_bounds__(256, 3) void gemm_kernel(float* __restrict__ out) {
    extern __shared__ char dsm[];
    const uint32_t sb = smem_u32(dsm);
    const int tid = threadIdx.x;
    const int lane = tid & 31, wid = tid >> 5;
    const int wn = wid >> 1, wm = wid & 1;          // warp tile: 32n x 32m (4n x 2m warps)
    const int n0 = (blockIdx.x & 1) * 128;
    const int m0 = (blockIdx.x >> 1) * 64;          // adjacent blocks share the B tile (L2)
    const int tg = lane & 3, gp = lane >> 2;        // threadID_in_group, groupID

    float c[2][4][4];
#pragma unroll
    for (int a = 0; a < 2; ++a)
#pragma unroll
        for (int b = 0; b < 4; ++b)
#pragma unroll
            for (int d = 0; d < 4; ++d) c[a][b][d] = 0.0f;

    auto load_stage = [&](int st, int kt) {
        uint32_t ab = sb + st * STG, bb = ab + ASTG;
#pragma unroll
        for (int it = 0; it < 2; ++it) {
            int e = tid + it * 256;                       // 0..511
            // A: 128 n-rows x 4 chunks of 16B (k 0..31)
            int r = e >> 2, q = e & 3;
            CPA(ab + r * 80 + q * 16, g_wh + (size_t)(n0 + r) * 1024 + kt * 32 + q * 8);
        }
        {   // B: 16 kp-rows x 4 chunks of 16B (64 m as u32)
            int r = tid >> 4, q = tid & 15;
            CPA(bb + r * 288 + q * 16, g_Bh + (size_t)(kt * 16 + r) * M_TOT + m0 + q * 4);
        }
        asm volatile("cp.async.commit_group;");
    };

    auto compute = [&](int st) {
        uint32_t ab = sb + st * STG, bb = ab + ASTG;
#pragma unroll
        for (int ks = 0; ks < 2; ++ks) {
            // B fragments: b0 at kp = ks*8+tg, b1 at kp+4; col = wm*32 + nj*8 + gp
            uint32_t bh0[4], bh1[4];
#pragma unroll
            for (int nj = 0; nj < 4; ++nj) {
                uint32_t off = bb + (ks * 8 + tg) * 288 + (wm * 32 + nj * 8 + gp) * 4;
                bh0[nj] = lds32(off);
                bh1[nj] = lds32(off + 4 * 288);
            }
#pragma unroll
            for (int mi = 0; mi < 2; ++mi) {
                // A fragments: row = wn*32+mi*16+gp(+8), k = ks*16 + 2*tg (+8)
                uint32_t ah[4];
                uint32_t aa = ab + (wn * 32 + mi * 16 + gp) * 80 + ks * 32 + tg * 4;
                ah[0] = lds32(aa);        ah[1] = lds32(aa + 640);
                ah[2] = lds32(aa + 16);   ah[3] = lds32(aa + 656);
#pragma unroll
                for (int nj = 0; nj < 4; ++nj)
                    MMA(c[mi][nj], ah, bh0[nj], bh1[nj]);
            }
        }
    };

    load_stage(0, 0);
    for (int t = 0; t < 32; ++t) {
        if (t + 1 < 32) {
            load_stage((t + 1) & 1, t + 1);
            asm volatile("cp.async.wait_group 1;");
        } else {
            asm volatile("cp.async.wait_group 0;");
        }
        __syncthreads();
        compute(t & 1);
        __syncthreads();
    }

    // epilogue: c frag (row=gp, col=2*tg) -> smem [128][68] -> coalesced float4
    float* ep = (float*)dsm;
#pragma unroll
    for (int mi = 0; mi < 2; ++mi)
#pragma unroll
        for (int nj = 0; nj < 4; ++nj) {
            int n1 = wn * 32 + mi * 16 + gp;
            int m1 = wm * 32 + nj * 8 + tg * 2;
            *(float2*)&ep[n1 * 68 + m1] = make_float2(c[mi][nj][0], c[mi][nj][1]);
            *(float2*)&ep[(n1 + 8) * 68 + m1] = make_float2(c[mi][nj][2], c[mi][nj][3]);
        }
    __syncthreads();
#pragma unroll
    for (int it = 0; it < 8; ++it) {
        int e = tid + it * 256;                 // 0..2047
        int row = e >> 4, q = e & 15;
        int mg = m0 + q * 4;
        int bb2 = mg / 784, ij = mg - bb2 * 784;
        float4 v = *(float4*)&ep[row * 68 + q * 4];
        *(float4*)&out[((size_t)bb2 * 256 + n0 + row) * 784 + ij] = v;
    }
}

extern "C" void kernel_launch(void* const* d_in, const int* in_sizes, int n_in,
                              void* d_out, int out_size) {
    (void)in_sizes; (void)n_in; (void)out_size;
    const float* x     = (const float*)d_in[0];
    const float* gamma = (const float*)d_in[1];
    const float* beta  = (const float*)d_in[2];
    const float* mean  = (const float*)d_in[3];
    const float* var   = (const float*)d_in[4];
    const float* w     = (const float*)d_in[5];
    float* out = (float*)d_out;

    cudaFuncSetAttribute(gemm_kernel, cudaFuncAttributeMaxDynamicSharedMemorySize, DSMEM);
    pass1_kernel<<<8448, 256>>>(x, gamma, beta, mean, var, w);
    gemm_kernel<<<784, 256, DSMEM>>>(out);
}

// round 13
// speedup vs baseline: 1.0784x; 1.0784x over previous
#include <cuda_runtime.h>
#include <cuda_fp16.h>
#include <cstdint>

#define M_TOT 25088
#define ASTG 10240          // A bytes/stage: 128 n-rows padded to 80B
#define BSTG 8704           // B bytes/stage: 16 kp-rows x 128 m (u32), padded to 544B
#define STG  18944
#define DSMEM 37888

__device__ __align__(256) uint32_t g_Bh[12845056];        // hbar fp16 [512 kp][25088 m], k-pair packed
__device__ __align__(256) unsigned short g_wh[262144];    // W fp16 [n][k]

__device__ __forceinline__ int rmap(int p) { int q = p / 7, r = p - q * 7; return q * 6 + (r < 5 ? r : 5) + 4; }
__device__ __forceinline__ uint32_t smem_u32(const void* p) {
    uint32_t a; asm("{ .reg .u64 t; cvta.to.shared.u64 t, %1; cvt.u32.u64 %0, t; }" : "=r"(a) : "l"(p)); return a;
}
__device__ __forceinline__ uint32_t lds32(uint32_t a) {
    uint32_t v; asm volatile("ld.shared.u32 %0, [%1];" : "=r"(v) : "r"(a)); return v;
}

#define LDSM(r, a) asm volatile("ldmatrix.sync.aligned.m8n8.x4.shared.b16 {%0,%1,%2,%3}, [%4];" \
    : "=r"((r)[0]), "=r"((r)[1]), "=r"((r)[2]), "=r"((r)[3]) : "r"(a))
#define MMA(c, a, b0, b1) asm volatile( \
    "mma.sync.aligned.m16n8k16.row.col.f32.f16.f16.f32 {%0,%1,%2,%3}, {%4,%5,%6,%7}, {%8,%9}, {%0,%1,%2,%3};" \
    : "+f"((c)[0]), "+f"((c)[1]), "+f"((c)[2]), "+f"((c)[3]) \
    : "r"((a)[0]), "r"((a)[1]), "r"((a)[2]), "r"((a)[3]), "r"(b0), "r"(b1))
#define CPA(d, s) asm volatile("cp.async.cg.shared.global [%0], [%1], 16;" :: "r"(d), "l"(s))

// ---- pass1 (+ folded W prep): blocks >= 8192 convert W; others gather+BN+ReLU+pool
__global__ __launch_bounds__(256) void pass1_kernel(const float* __restrict__ x,
        const float* __restrict__ gamma, const float* __restrict__ beta,
        const float* __restrict__ mean, const float* __restrict__ var,
        const float* __restrict__ w) {
    __shared__ float s[2][3136];
    int t = threadIdx.x, blk = blockIdx.x;

    if (blk >= 8192) {                           // W f32 -> fp16 [n][k], 4 elems/thread
        int i = (blk - 8192) * 256 + t;          // 0..65535
        float4 v = *(const float4*)(w + (size_t)i * 4);
        __half2 p0 = __floats2half2_rn(v.x, v.y);
        __half2 p1 = __floats2half2_rn(v.z, v.w);
        *(uint2*)(g_wh + (size_t)i * 4) = make_uint2(*(uint32_t*)&p0, *(uint32_t*)&p1);
        return;
    }

    int b = blk & 31, cp = blk >> 5;             // cp 0..255 -> channels 2cp, 2cp+1
#pragma unroll
    for (int pl = 0; pl < 2; ++pl) {
        const float4* xp4 = (const float4*)(x + ((size_t)(b * 512 + 2 * cp + pl)) * 3136);
        float4* s4 = (float4*)s[pl];
        // 784 float4 = 3*256 + 16
        s4[t] = xp4[t];
        s4[t + 256] = xp4[t + 256];
        s4[t + 512] = xp4[t + 512];
        if (t < 16) s4[t + 768] = xp4[t + 768];
    }
    __syncthreads();
    if (t >= 196) return;
    int ij0 = 4 * t, i = ij0 / 28, j0 = ij0 - i * 28;
#pragma unroll
    for (int g = 0; g < 2; ++g) {                // g=0 direct, g=1 gathered (+512)
        unsigned short hh[2][4];
#pragma unroll
        for (int pl = 0; pl < 2; ++pl) {
            int c2 = 2 * cp + pl + g * 512;
            float inv = gamma[c2] * rsqrtf(var[c2] + 1e-5f);
            float bias = fmaf(-mean[c2], inv, beta[c2]);
            const float* r0; const float* r1;
            if (!g) { r0 = s[pl] + (2 * i) * 56; r1 = r0 + 56; }
            else { r0 = s[pl] + rmap(2 * i) * 56; r1 = s[pl] + rmap(2 * i + 1) * 56; }
#pragma unroll
            for (int u = 0; u < 4; ++u) {
                int jj = j0 + u;
                int q0 = g ? rmap(2 * jj) : 2 * jj;
                int q1 = g ? rmap(2 * jj + 1) : 2 * jj + 1;
                float o = 0.25f * (fmaxf(fmaf(r0[q0], inv, bias), 0.0f) + fmaxf(fmaf(r0[q1], inv, bias), 0.0f)
                                 + fmaxf(fmaf(r1[q0], inv, bias), 0.0f) + fmaxf(fmaf(r1[q1], inv, bias), 0.0f));
                __half hv = __float2half_rn(o);
                hh[pl][u] = *(unsigned short*)&hv;
            }
        }
        size_t base = (size_t)(g * 256 + cp) * M_TOT + b * 784 + ij0;
        uint4 vh;
        vh.x = hh[0][0] | ((uint32_t)hh[1][0] << 16); vh.y = hh[0][1] | ((uint32_t)hh[1][1] << 16);
        vh.z = hh[0][2] | ((uint32_t)hh[1][2] << 16); vh.w = hh[0][3] | ((uint32_t)hh[1][3] << 16);
        *(uint4*)(g_Bh + base) = vh;
    }
}

// ---- pass2: fp16 HMMA GEMM, tile 128n x 128m (R10 geometry), ldmatrix A -----
__global__ __launch_bounds__(256, 2) void gemm_kernel(float* __restrict__ out) {
    extern __shared__ char dsm[];
    const uint32_t sb = smem_u32(dsm);
    const int tid = threadIdx.x;
    const int lane = tid & 31, wid = tid >> 5;
    const int wn = wid >> 2, wm = wid & 3;          // warp tile: 64n x 32m
    const int n0 = (blockIdx.x & 1) * 128;
    const int m0 = (blockIdx.x >> 1) * 128;
    const int tg = lane & 3, gp = lane >> 2;        // threadID_in_group, groupID

    float c[4][4][4];
#pragma unroll
    for (int a = 0; a < 4; ++a)
#pragma unroll
        for (int b = 0; b < 4; ++b)
#pragma unroll
            for (int d = 0; d < 4; ++d) c[a][b][d] = 0.0f;

    auto load_stage = [&](int st, int kt) {
        uint32_t ab = sb + st * STG, bb = ab + ASTG;
#pragma unroll
        for (int it = 0; it < 2; ++it) {
            int e = tid + it * 256;                       // 0..511
            {   // A: 128 n-rows x 4 chunks of 16B (k 0..31)
                int r = e >> 2, q = e & 3;
                CPA(ab + r * 80 + q * 16, g_wh + (size_t)(n0 + r) * 1024 + kt * 32 + q * 8);
            }
            {   // B: 16 kp-rows x 32 chunks of 16B (m 0..127 as u32)
                int r = e >> 5, q = e & 31;
                CPA(bb + r * 544 + q * 16, g_Bh + (size_t)(kt * 16 + r) * M_TOT + m0 + q * 4);
            }
        }
        asm volatile("cp.async.commit_group;");
    };

    auto compute = [&](int st) {
        uint32_t ab = sb + st * STG, bb = ab + ASTG;
#pragma unroll
        for (int ks = 0; ks < 2; ++ks) {
            // B fragments: b0 at kp = ks*8+tg, b1 at kp+4; col = wm*32 + nj*8 + gp
            uint32_t bh0[4], bh1[4];
#pragma unroll
            for (int nj = 0; nj < 4; ++nj) {
                uint32_t off = bb + (ks * 8 + tg) * 544 + (wm * 32 + nj * 8 + gp) * 4;
                bh0[nj] = lds32(off);
                bh1[nj] = lds32(off + 4 * 544);
            }
#pragma unroll
            for (int mi = 0; mi < 4; ++mi) {
                // A fragment via ldmatrix.x4: row = wn*64+mi*16+(lane&15), 16B-block = lane>>4
                uint32_t ah[4];
                LDSM(ah, ab + (wn * 64 + mi * 16 + (lane & 15)) * 80 + ks * 32 + (lane >> 4) * 16);
#pragma unroll
                for (int nj = 0; nj < 4; ++nj)
                    MMA(c[mi][nj], ah, bh0[nj], bh1[nj]);
            }
        }
    };

    load_stage(0, 0);
    for (int t = 0; t < 32; ++t) {
        if (t + 1 < 32) {
            load_stage((t + 1) & 1, t + 1);
            asm volatile("cp.async.wait_group 1;");
        } else {
            asm volatile("cp.async.wait_group 0;");
        }
        __syncthreads();
        compute(t & 1);
        __syncthreads();
    }

    // epilogue in two 64-row halves: c frag (row=gp, col=2*tg) -> smem -> coalesced
    float* ep = (float*)dsm;                    // [64 n][132 m] f32
#pragma unroll
    for (int h = 0; h < 2; ++h) {
        __syncthreads();
        if (wn == h) {
#pragma unroll
            for (int mi = 0; mi < 4; ++mi)
#pragma unroll
                for (int nj = 0; nj < 4; ++nj) {
                    int n1 = mi * 16 + gp;
                    int m1 = wm * 32 + nj * 8 + tg * 2;
                    *(float2*)&ep[n1 * 132 + m1] = make_float2(c[mi][nj][0], c[mi][nj][1]);
                    *(float2*)&ep[(n1 + 8) * 132 + m1] = make_float2(c[mi][nj][2], c[mi][nj][3]);
                }
        }
        __syncthreads();
#pragma unroll
        for (int it = 0; it < 8; ++it) {
            int e = tid + it * 256;             // 0..2047
            int row = e >> 5, q = e & 31;
            int mg = m0 + q * 4;
            int bb2 = mg / 784, ij = mg - bb2 * 784;
            float4 v = *(float4*)&ep[row * 132 + q * 4];
            *(float4*)&out[((size_t)bb2 * 256 + n0 + h * 64 + row) * 784 + ij] = v;
        }
    }
}

extern "C" void kernel_launch(void* const* d_in, const int* in_sizes, int n_in,
                              void* d_out, int out_size) {
    (void)in_sizes; (void)n_in; (void)out_size;
    const float* x     = (const float*)d_in[0];
    const float* gamma = (const float*)d_in[1];
    const float* beta  = (const float*)d_in[2];
    const float* mean  = (const float*)d_in[3];
    const float* var   = (const float*)d_in[4];
    const float* w     = (const float*)d_in[5];
    float* out = (float*)d_out;

    cudaFuncSetAttribute(gemm_kernel, cudaFuncAttributeMaxDynamicSharedMemorySize, DSMEM);
    pass1_kernel<<<8448, 256>>>(x, gamma, beta, mean, var, w);
    gemm_kernel<<<392, 256, DSMEM>>>(out);
}

// round 14
// speedup vs baseline: 1.1438x; 1.0606x over previous
#include <cuda_runtime.h>
#include <cuda_fp16.h>
#include <cstdint>

#define M_TOT 25088
#define ASTG 10240          // A bytes/stage: 128 n-rows padded to 80B
#define BSTG 8704           // B bytes/stage: 16 kp-rows x 128 m (u32), padded to 544B
#define STG  18944
#define DSMEM 75776         // 4 pipeline stages

__device__ __align__(256) uint32_t g_Bh[12845056];        // hbar fp16 [512 kp][25088 m], k-pair packed
__device__ __align__(256) unsigned short g_wh[262144];    // W fp16 [n][k]

__device__ __forceinline__ int rmap(int p) { int q = p / 7, r = p - q * 7; return q * 6 + (r < 5 ? r : 5) + 4; }
__device__ __forceinline__ uint32_t smem_u32(const void* p) {
    uint32_t a; asm("{ .reg .u64 t; cvta.to.shared.u64 t, %1; cvt.u32.u64 %0, t; }" : "=r"(a) : "l"(p)); return a;
}
__device__ __forceinline__ uint32_t lds32(uint32_t a) {
    uint32_t v; asm volatile("ld.shared.u32 %0, [%1];" : "=r"(v) : "r"(a)); return v;
}

#define LDSM(r, a) asm volatile("ldmatrix.sync.aligned.m8n8.x4.shared.b16 {%0,%1,%2,%3}, [%4];" \
    : "=r"((r)[0]), "=r"((r)[1]), "=r"((r)[2]), "=r"((r)[3]) : "r"(a))
#define MMA(c, a, b0, b1) asm volatile( \
    "mma.sync.aligned.m16n8k16.row.col.f32.f16.f16.f32 {%0,%1,%2,%3}, {%4,%5,%6,%7}, {%8,%9}, {%0,%1,%2,%3};" \
    : "+f"((c)[0]), "+f"((c)[1]), "+f"((c)[2]), "+f"((c)[3]) \
    : "r"((a)[0]), "r"((a)[1]), "r"((a)[2]), "r"((a)[3]), "r"(b0), "r"(b1))
#define CPA(d, s) asm volatile("cp.async.cg.shared.global [%0], [%1], 16;" :: "r"(d), "l"(s))

// ---- pass1 (+ folded W prep): blocks >= 8192 convert W; others gather+BN+ReLU+pool
__global__ __launch_bounds__(256) void pass1_kernel(const float* __restrict__ x,
        const float* __restrict__ gamma, const float* __restrict__ beta,
        const float* __restrict__ mean, const float* __restrict__ var,
        const float* __restrict__ w) {
    __shared__ float s[2][3136];
    int t = threadIdx.x, blk = blockIdx.x;

    if (blk >= 8192) {                           // W f32 -> fp16 [n][k], 4 elems/thread
        int i = (blk - 8192) * 256 + t;          // 0..65535
        float4 v = *(const float4*)(w + (size_t)i * 4);
        __half2 p0 = __floats2half2_rn(v.x, v.y);
        __half2 p1 = __floats2half2_rn(v.z, v.w);
        *(uint2*)(g_wh + (size_t)i * 4) = make_uint2(*(uint32_t*)&p0, *(uint32_t*)&p1);
        return;
    }

    int b = blk & 31, cp = blk >> 5;             // cp 0..255 -> channels 2cp, 2cp+1
#pragma unroll
    for (int pl = 0; pl < 2; ++pl) {
        const float4* xp4 = (const float4*)(x + ((size_t)(b * 512 + 2 * cp + pl)) * 3136);
        float4* s4 = (float4*)s[pl];
        // 784 float4 = 3*256 + 16
        s4[t] = xp4[t];
        s4[t + 256] = xp4[t + 256];
        s4[t + 512] = xp4[t + 512];
        if (t < 16) s4[t + 768] = xp4[t + 768];
    }
    __syncthreads();
    if (t >= 196) return;
    int ij0 = 4 * t, i = ij0 / 28, j0 = ij0 - i * 28;
#pragma unroll
    for (int g = 0; g < 2; ++g) {                // g=0 direct, g=1 gathered (+512)
        unsigned short hh[2][4];
#pragma unroll
        for (int pl = 0; pl < 2; ++pl) {
            int c2 = 2 * cp + pl + g * 512;
            float inv = gamma[c2] * rsqrtf(var[c2] + 1e-5f);
            float bias = fmaf(-mean[c2], inv, beta[c2]);
            const float* r0; const float* r1;
            if (!g) { r0 = s[pl] + (2 * i) * 56; r1 = r0 + 56; }
            else { r0 = s[pl] + rmap(2 * i) * 56; r1 = s[pl] + rmap(2 * i + 1) * 56; }
#pragma unroll
            for (int u = 0; u < 4; ++u) {
                int jj = j0 + u;
                int q0 = g ? rmap(2 * jj) : 2 * jj;
                int q1 = g ? rmap(2 * jj + 1) : 2 * jj + 1;
                float o = 0.25f * (fmaxf(fmaf(r0[q0], inv, bias), 0.0f) + fmaxf(fmaf(r0[q1], inv, bias), 0.0f)
                                 + fmaxf(fmaf(r1[q0], inv, bias), 0.0f) + fmaxf(fmaf(r1[q1], inv, bias), 0.0f));
                __half hv = __float2half_rn(o);
                hh[pl][u] = *(unsigned short*)&hv;
            }
        }
        size_t base = (size_t)(g * 256 + cp) * M_TOT + b * 784 + ij0;
        uint4 vh;
        vh.x = hh[0][0] | ((uint32_t)hh[1][0] << 16); vh.y = hh[0][1] | ((uint32_t)hh[1][1] << 16);
        vh.z = hh[0][2] | ((uint32_t)hh[1][2] << 16); vh.w = hh[0][3] | ((uint32_t)hh[1][3] << 16);
        *(uint4*)(g_Bh + base) = vh;
    }
}

// ---- pass2: fp16 HMMA GEMM, 128n x 128m, 4-stage cp.async ring, 1 bar/chunk -
__global__ __launch_bounds__(256, 2) void gemm_kernel(float* __restrict__ out) {
    extern __shared__ char dsm[];
    const uint32_t sb = smem_u32(dsm);
    const int tid = threadIdx.x;
    const int lane = tid & 31, wid = tid >> 5;
    const int wn = wid >> 2, wm = wid & 3;          // warp tile: 64n x 32m
    const int n0 = (blockIdx.x & 1) * 128;
    const int m0 = (blockIdx.x >> 1) * 128;
    const int tg = lane & 3, gp = lane >> 2;        // threadID_in_group, groupID

    float c[4][4][4];
#pragma unroll
    for (int a = 0; a < 4; ++a)
#pragma unroll
        for (int b = 0; b < 4; ++b)
#pragma unroll
            for (int d = 0; d < 4; ++d) c[a][b][d] = 0.0f;

    auto load_stage = [&](int st, int kt) {
        uint32_t ab = sb + st * STG, bb = ab + ASTG;
#pragma unroll
        for (int it = 0; it < 2; ++it) {
            int e = tid + it * 256;                       // 0..511
            {   // A: 128 n-rows x 4 chunks of 16B (k 0..31)
                int r = e >> 2, q = e & 3;
                CPA(ab + r * 80 + q * 16, g_wh + (size_t)(n0 + r) * 1024 + kt * 32 + q * 8);
            }
            {   // B: 16 kp-rows x 32 chunks of 16B (m 0..127 as u32)
                int r = e >> 5, q = e & 31;
                CPA(bb + r * 544 + q * 16, g_Bh + (size_t)(kt * 16 + r) * M_TOT + m0 + q * 4);
            }
        }
        asm volatile("cp.async.commit_group;");
    };

    auto compute = [&](int st) {
        uint32_t ab = sb + st * STG, bb = ab + ASTG;
#pragma unroll
        for (int ks = 0; ks < 2; ++ks) {
            // B fragments: b0 at kp = ks*8+tg, b1 at kp+4; col = wm*32 + nj*8 + gp
            uint32_t bh0[4], bh1[4];
#pragma unroll
            for (int nj = 0; nj < 4; ++nj) {
                uint32_t off = bb + (ks * 8 + tg) * 544 + (wm * 32 + nj * 8 + gp) * 4;
                bh0[nj] = lds32(off);
                bh1[nj] = lds32(off + 4 * 544);
            }
#pragma unroll
            for (int mi = 0; mi < 4; ++mi) {
                // A fragment via ldmatrix.x4: row = wn*64+mi*16+(lane&15), 16B-block = lane>>4
                uint32_t ah[4];
                LDSM(ah, ab + (wn * 64 + mi * 16 + (lane & 15)) * 80 + ks * 32 + (lane >> 4) * 16);
#pragma unroll
                for (int nj = 0; nj < 4; ++nj)
                    MMA(c[mi][nj], ah, bh0[nj], bh1[nj]);
            }
        }
    };

    // prologue: fill 3 of 4 stages, ensure stage 0 landed
    load_stage(0, 0);
    load_stage(1, 1);
    load_stage(2, 2);
    asm volatile("cp.async.wait_group 2;");
    __syncthreads();

    for (int t = 0; t < 32; ++t) {
        compute(t & 3);
        if (t + 3 < 32) {
            load_stage((t + 3) & 3, t + 3);
            asm volatile("cp.async.wait_group 2;");     // group t+1 complete
        } else {
            asm volatile("cp.async.wait_group 0;");     // drain tail
        }
        __syncthreads();
    }

    // epilogue in two 64-row halves: c frag (row=gp, col=2*tg) -> smem -> coalesced
    float* ep = (float*)dsm;                    // [64 n][132 m] f32
#pragma unroll
    for (int h = 0; h < 2; ++h) {
        __syncthreads();
        if (wn == h) {
#pragma unroll
            for (int mi = 0; mi < 4; ++mi)
#pragma unroll
                for (int nj = 0; nj < 4; ++nj) {
                    int n1 = mi * 16 + gp;
                    int m1 = wm * 32 + nj * 8 + tg * 2;
                    *(float2*)&ep[n1 * 132 + m1] = make_float2(c[mi][nj][0], c[mi][nj][1]);
                    *(float2*)&ep[(n1 + 8) * 132 + m1] = make_float2(c[mi][nj][2], c[mi][nj][3]);
                }
        }
        __syncthreads();
#pragma unroll
        for (int it = 0; it < 8; ++it) {
            int e = tid + it * 256;             // 0..2047
            int row = e >> 5, q = e & 31;
            int mg = m0 + q * 4;
            int bb2 = mg / 784, ij = mg - bb2 * 784;
            float4 v = *(float4*)&ep[row * 132 + q * 4];
            *(float4*)&out[((size_t)bb2 * 256 + n0 + h * 64 + row) * 784 + ij] = v;
        }
    }
}

extern "C" void kernel_launch(void* const* d_in, const int* in_sizes, int n_in,
                              void* d_out, int out_size) {
    (void)in_sizes; (void)n_in; (void)out_size;
    const float* x     = (const float*)d_in[0];
    const float* gamma = (const float*)d_in[1];
    const float* beta  = (const float*)d_in[2];
    const float* mean  = (const float*)d_in[3];
    const float* var   = (const float*)d_in[4];
    const float* w     = (const float*)d_in[5];
    float* out = (float*)d_out;

    cudaFuncSetAttribute(gemm_kernel, cudaFuncAttributeMaxDynamicSharedMemorySize, DSMEM);
    pass1_kernel<<<8448, 256>>>(x, gamma, beta, mean, var, w);
    gemm_kernel<<<392, 256, DSMEM>>>(out);
}

// round 15
// speedup vs baseline: 1.1894x; 1.0399x over previous
#include <cuda_runtime.h>
#include <cuda_fp16.h>
#include <cstdint>

#define M_TOT 25088
#define ASTG 10240          // A/stage: 128 n-rows x 32k fp16, rows padded to 80B
#define BSTG 8704           // B/stage: 32 k-rows x 128m fp16, rows padded to 272B
#define STG  18944
#define NSTG 6
#define DSMEM (STG * NSTG)  // 113664

__device__ __align__(256) unsigned short g_B[25690112];   // hbar fp16 [1024 k][25088 m]
__device__ __align__(256) unsigned short g_wh[262144];    // W fp16 [n][k]

__device__ __forceinline__ int rmap(int p) { int q = p / 7, r = p - q * 7; return q * 6 + (r < 5 ? r : 5) + 4; }
__device__ __forceinline__ uint32_t smem_u32(const void* p) {
    uint32_t a; asm("{ .reg .u64 t; cvta.to.shared.u64 t, %1; cvt.u32.u64 %0, t; }" : "=r"(a) : "l"(p)); return a;
}

#define LDSM(r, a) asm volatile("ldmatrix.sync.aligned.m8n8.x4.shared.b16 {%0,%1,%2,%3}, [%4];" \
    : "=r"((r)[0]), "=r"((r)[1]), "=r"((r)[2]), "=r"((r)[3]) : "r"(a))
#define LDSMT(r, a) asm volatile("ldmatrix.sync.aligned.m8n8.x4.trans.shared.b16 {%0,%1,%2,%3}, [%4];" \
    : "=r"((r)[0]), "=r"((r)[1]), "=r"((r)[2]), "=r"((r)[3]) : "r"(a))
#define MMA(c, a, b0, b1) asm volatile( \
    "mma.sync.aligned.m16n8k16.row.col.f32.f16.f16.f32 {%0,%1,%2,%3}, {%4,%5,%6,%7}, {%8,%9}, {%0,%1,%2,%3};" \
    : "+f"((c)[0]), "+f"((c)[1]), "+f"((c)[2]), "+f"((c)[3]) \
    : "r"((a)[0]), "r"((a)[1]), "r"((a)[2]), "r"((a)[3]), "r"(b0), "r"(b1))
#define CPA(d, s) asm volatile("cp.async.cg.shared.global [%0], [%1], 16;" :: "r"(d), "l"(s))

// ---- pass1 (+ folded W prep): blocks >= 16384 convert W; others gather+BN+ReLU+pool
__global__ __launch_bounds__(256) void pass1_kernel(const float* __restrict__ x,
        const float* __restrict__ gamma, const float* __restrict__ beta,
        const float* __restrict__ mean, const float* __restrict__ var,
        const float* __restrict__ w) {
    __shared__ float s[3136];
    int t = threadIdx.x, blk = blockIdx.x;

    if (blk >= 16384) {                          // W f32 -> fp16 [n][k], 4 elems/thread
        int i = (blk - 16384) * 256 + t;         // 0..65535
        float4 v = *(const float4*)(w + (size_t)i * 4);
        __half2 p0 = __floats2half2_rn(v.x, v.y);
        __half2 p1 = __floats2half2_rn(v.z, v.w);
        *(uint2*)(g_wh + (size_t)i * 4) = make_uint2(*(uint32_t*)&p0, *(uint32_t*)&p1);
        return;
    }

    int b = blk & 31, c = blk >> 5;              // c 0..511
    {
        const float4* xp4 = (const float4*)(x + (size_t)(b * 512 + c) * 3136);
        float4* s4 = (float4*)s;
        // 784 float4 = 3*256 + 16
        s4[t] = xp4[t];
        s4[t + 256] = xp4[t + 256];
        s4[t + 512] = xp4[t + 512];
        if (t < 16) s4[t + 768] = xp4[t + 768];
    }
    __syncthreads();
    if (t >= 196) return;
    int ij0 = 4 * t, i = ij0 / 28, j0 = ij0 - i * 28;
#pragma unroll
    for (int g = 0; g < 2; ++g) {                // g=0 direct, g=1 gathered (+512)
        int c2 = c + g * 512;
        float inv = gamma[c2] * rsqrtf(var[c2] + 1e-5f);
        float bias = fmaf(-mean[c2], inv, beta[c2]);
        const float* r0; const float* r1;
        if (!g) { r0 = s + (2 * i) * 56; r1 = r0 + 56; }
        else { r0 = s + rmap(2 * i) * 56; r1 = s + rmap(2 * i + 1) * 56; }
        unsigned short hh[4];
#pragma unroll
        for (int u = 0; u < 4; ++u) {
            int jj = j0 + u;
            int q0 = g ? rmap(2 * jj) : 2 * jj;
            int q1 = g ? rmap(2 * jj + 1) : 2 * jj + 1;
            float o = 0.25f * (fmaxf(fmaf(r0[q0], inv, bias), 0.0f) + fmaxf(fmaf(r0[q1], inv, bias), 0.0f)
                             + fmaxf(fmaf(r1[q0], inv, bias), 0.0f) + fmaxf(fmaf(r1[q1], inv, bias), 0.0f));
            __half hv = __float2half_rn(o);
            hh[u] = *(unsigned short*)&hv;
        }
        *(uint2*)(g_B + (size_t)c2 * M_TOT + b * 784 + ij0) =
            make_uint2(hh[0] | ((uint32_t)hh[1] << 16), hh[2] | ((uint32_t)hh[3] << 16));
    }
}

// ---- pass2: fp16 HMMA GEMM, 128n x 128m, 6-stage ring, ldmatrix A+B --------
__global__ __launch_bounds__(256, 2) void gemm_kernel(float* __restrict__ out) {
    extern __shared__ char dsm[];
    const uint32_t sb = smem_u32(dsm);
    const int tid = threadIdx.x;
    const int lane = tid & 31, wid = tid >> 5;
    const int wn = wid >> 2, wm = wid & 3;          // warp tile: 64n x 32m
    const int n0 = (blockIdx.x & 1) * 128;
    const int m0 = (blockIdx.x >> 1) * 128;
    const int tg = lane & 3, gp = lane >> 2;

    float c[4][4][4];
#pragma unroll
    for (int a = 0; a < 4; ++a)
#pragma unroll
        for (int b = 0; b < 4; ++b)
#pragma unroll
            for (int d = 0; d < 4; ++d) c[a][b][d] = 0.0f;

    auto load_stage = [&](int st, int kt) {
        uint32_t ab = sb + st * STG, bb = ab + ASTG;
#pragma unroll
        for (int it = 0; it < 2; ++it) {
            int e = tid + it * 256;                       // 0..511
            {   // A: 128 n-rows x 4 chunks of 16B (k 0..31)
                int r = e >> 2, q = e & 3;
                CPA(ab + r * 80 + q * 16, g_wh + (size_t)(n0 + r) * 1024 + kt * 32 + q * 8);
            }
            {   // B: 32 k-rows x 16 chunks of 16B (m 0..127)
                int r = e >> 4, q = e & 15;
                CPA(bb + r * 272 + q * 16, g_B + (size_t)(kt * 32 + r) * M_TOT + m0 + q * 8);
            }
        }
        asm volatile("cp.async.commit_group;");
    };

    auto compute = [&](int st) {
        uint32_t ab = sb + st * STG, bb = ab + ASTG;
#pragma unroll
        for (int ks = 0; ks < 2; ++ks) {
            // B frags via ldmatrix.x4.trans (R5-validated geometry):
            // rows = ks*16 + (lane&15); col block = wm*32 + (lane>>4)*8 m
            uint32_t bh[8];
            uint32_t ba = bb + (ks * 16 + (lane & 15)) * 272 + (wm * 32 + (lane >> 4) * 8) * 2;
            LDSMT(&bh[0], ba);            // m[0:16]  -> nj 0,1
            LDSMT(&bh[4], ba + 32);       // m[16:32] -> nj 2,3
#pragma unroll
            for (int mi = 0; mi < 4; ++mi) {
                uint32_t ah[4];
                LDSM(ah, ab + (wn * 64 + mi * 16 + (lane & 15)) * 80 + ks * 32 + (lane >> 4) * 16);
#pragma unroll
                for (int nj = 0; nj < 4; ++nj)
                    MMA(c[mi][nj], ah, bh[nj * 2], bh[nj * 2 + 1]);
            }
        }
    };

    // prologue: fill 4 of 6 stages; ensure stages 0,1 landed
    load_stage(0, 0); load_stage(1, 1); load_stage(2, 2); load_stage(3, 3);
    asm volatile("cp.async.wait_group 2;");
    __syncthreads();

    for (int t = 0; t < 32; t += 2) {
        compute(t % 6);
        compute((t + 1) % 6);
        if (t + 4 < 32) {
            load_stage((t + 4) % 6, t + 4);
            load_stage((t + 5) % 6, t + 5);
            asm volatile("cp.async.wait_group 2;");   // t+2, t+3 landed
        } else {
            asm volatile("cp.async.wait_group 0;");
        }
        __syncthreads();
    }

    // epilogue in two 64-row halves: c frag (row=gp, col=2*tg) -> smem -> coalesced
    float* ep = (float*)dsm;                    // [64 n][132 m] f32
#pragma unroll
    for (int h = 0; h < 2; ++h) {
        __syncthreads();
        if (wn == h) {
#pragma unroll
            for (int mi = 0; mi < 4; ++mi)
#pragma unroll
                for (int nj = 0; nj < 4; ++nj) {
                    int n1 = mi * 16 + gp;
                    int m1 = wm * 32 + nj * 8 + tg * 2;
                    *(float2*)&ep[n1 * 132 + m1] = make_float2(c[mi][nj][0], c[mi][nj][1]);
                    *(float2*)&ep[(n1 + 8) * 132 + m1] = make_float2(c[mi][nj][2], c[mi][nj][3]);
                }
        }
        __syncthreads();
#pragma unroll
        for (int it = 0; it < 8; ++it) {
            int e = tid + it * 256;             // 0..2047
            int row = e >> 5, q = e & 31;
            int mg = m0 + q * 4;
            int bb2 = mg / 784, ij = mg - bb2 * 784;
            float4 v = *(float4*)&ep[row * 132 + q * 4];
            *(float4*)&out[((size_t)bb2 * 256 + n0 + h * 64 + row) * 784 + ij] = v;
        }
    }
}

extern "C" void kernel_launch(void* const* d_in, const int* in_sizes, int n_in,
                              void* d_out, int out_size) {
    (void)in_sizes; (void)n_in; (void)out_size;
    const float* x     = (const float*)d_in[0];
    const float* gamma = (const float*)d_in[1];
    const float* beta  = (const float*)d_in[2];
    const float* mean  = (const float*)d_in[3];
    const float* var   = (const float*)d_in[4];
    const float* w     = (const float*)d_in[5];
    float* out = (float*)d_out;

    cudaFuncSetAttribute(gemm_kernel, cudaFuncAttributeMaxDynamicSharedMemorySize, DSMEM);
    pass1_kernel<<<16640, 256>>>(x, gamma, beta, mean, var, w);
    gemm_kernel<<<392, 256, DSMEM>>>(out);
}